// round 1
// baseline (speedup 1.0000x reference)
#include <cuda_runtime.h>
#include <cuda_bf16.h>

// Problem constants
#define Nn 8
#define Cc 16
#define Ll 32
#define Dd 24
#define Hh 24
#define WW 24
#define Ff 32
#define OL 30
#define OD 22
#define OH 22
#define OWc 22

// x slab per (n,l,d,c): 3(lk) x 3(dk) planes of 24x24
#define SLAB_ELEMS (9 * 576)      // 5184 floats = 20.7 KB
#define WSL_ELEMS  (16 * 81)      // 16 filters x 81 taps = 5.2 KB

__global__ __launch_bounds__(128, 4)
void conv4d_kernel(const float* __restrict__ x,
                   const float* __restrict__ Wt,
                   const float* __restrict__ bias,
                   float* __restrict__ out)
{
    __shared__ float sx[SLAB_ELEMS];   // [lk*3+dk][h][w]
    __shared__ float sw[WSL_ELEMS];    // [f][k]  k = ((lk*3+dk)*3+hk)*3+wk

    const int bid = blockIdx.x;
    const int fg  = bid & 1;           // filter group: 0 -> f 0..15, 1 -> f 16..31
    int t = bid >> 1;
    const int d = t % OD;  t /= OD;
    const int l = t % OL;
    const int n = t / OL;
    const int fbase = fg * 16;
    const int tid = threadIdx.x;

    // 11x11 grid of 2x2 output tiles covers 22x22
    const int ty = tid / 11;
    const int tx = tid % 11;
    const bool active = (tid < 121);
    const int oh0 = 2 * ty;
    const int ow0 = 2 * tx;

    float acc[16][4];
#pragma unroll
    for (int f = 0; f < 16; f++) {
        acc[f][0] = 0.f; acc[f][1] = 0.f; acc[f][2] = 0.f; acc[f][3] = 0.f;
    }

    // base pointer for (n, l, d) in x: strides w=1, h=24, d=576, l=13824, c=442368, n=7077888
    const float* xbase = x + (size_t)n * Cc * Ll * Dd * Hh * WW
                           + (size_t)l * Dd * Hh * WW
                           + (size_t)d * Hh * WW;

#pragma unroll 1
    for (int c = 0; c < Cc; c++) {
        __syncthreads();   // previous iteration's reads done before overwrite

        // ---- load x slab: 9 planes x 576 floats, vectorized float4 ----
        const float* xc = xbase + (size_t)c * Ll * Dd * Hh * WW;
#pragma unroll 1
        for (int i4 = tid; i4 < SLAB_ELEMS / 4; i4 += 128) {
            const int p  = i4 / 144;          // plane: lk*3+dk
            const int r4 = i4 - p * 144;      // float4 index within plane
            const int lk = p / 3;
            const int dk = p - lk * 3;
            const float4 v = *reinterpret_cast<const float4*>(
                xc + (size_t)lk * Dd * Hh * WW + (size_t)dk * Hh * WW + (size_t)r4 * 4);
            *reinterpret_cast<float4*>(&sx[p * 576 + r4 * 4]) = v;
        }

        // ---- load weights: 16 filters x 81 taps for this c ----
        // W layout (O,I,LK,DK,HK,WK): f stride 16*81=1296, c stride 81
        const float* wc = Wt + (size_t)fbase * (Cc * 81) + (size_t)c * 81;
#pragma unroll 1
        for (int i = tid; i < WSL_ELEMS; i += 128) {
            const int ff = i / 81;
            const int k  = i - ff * 81;
            sw[i] = wc[(size_t)ff * (Cc * 81) + k];
        }

        __syncthreads();

        if (active) {
#pragma unroll 1
            for (int lk = 0; lk < 3; lk++) {
#pragma unroll 1
                for (int dk = 0; dk < 3; dk++) {
                    const float* sxp = &sx[(lk * 3 + dk) * 576];
                    const int kbase = (lk * 3 + dk) * 9;
#pragma unroll
                    for (int hk = 0; hk < 3; hk++) {
                        const float* row0 = sxp + (oh0 + hk) * 24 + ow0;
                        const float* row1 = row0 + 24;
#pragma unroll
                        for (int wk = 0; wk < 3; wk++) {
                            const float x00 = row0[wk];
                            const float x01 = row0[wk + 1];
                            const float x10 = row1[wk];
                            const float x11 = row1[wk + 1];
                            const int k = kbase + hk * 3 + wk;
#pragma unroll
                            for (int f = 0; f < 16; f++) {
                                const float wv = sw[f * 81 + k];
                                acc[f][0] = fmaf(wv, x00, acc[f][0]);
                                acc[f][1] = fmaf(wv, x01, acc[f][1]);
                                acc[f][2] = fmaf(wv, x10, acc[f][2]);
                                acc[f][3] = fmaf(wv, x11, acc[f][3]);
                            }
                        }
                    }
                }
            }
        }
    }

    if (active) {
        // out dims (8,32,30,22,22,22)
#pragma unroll
        for (int f = 0; f < 16; f++) {
            const int fglob = fbase + f;
            const float bv = 3.0f * bias[fglob];
            const size_t obase =
                ((((size_t)n * Ff + fglob) * OL + l) * OD + d) * (OH * OWc);
            float2 v0 = make_float2(acc[f][0] + bv, acc[f][1] + bv);
            float2 v1 = make_float2(acc[f][2] + bv, acc[f][3] + bv);
            *reinterpret_cast<float2*>(&out[obase + (size_t)oh0 * OWc + ow0]) = v0;
            *reinterpret_cast<float2*>(&out[obase + (size_t)(oh0 + 1) * OWc + ow0]) = v1;
        }
    }
}

extern "C" void kernel_launch(void* const* d_in, const int* in_sizes, int n_in,
                              void* d_out, int out_size) {
    const float* x  = (const float*)d_in[0];
    const float* Wt = (const float*)d_in[1];
    const float* b  = (const float*)d_in[2];
    float* out = (float*)d_out;

    const int grid = Nn * OL * OD * 2;   // 8*30*22*2 = 10560 blocks
    conv4d_kernel<<<grid, 128>>>(x, Wt, b, out);
}

// round 3
// speedup vs baseline: 1.0233x; 1.0233x over previous
#include <cuda_runtime.h>
#include <cuda_bf16.h>

// Problem constants
#define Nn 8
#define Cc 16
#define Ll 32
#define Dd 24
#define Hh 24
#define WW 24
#define Ff 32
#define OL 30
#define OD 22
#define OH 22
#define OWc 22

#define SLAB_ELEMS (9 * 576)      // 5184 floats = 20.7 KB  [plane][h][w]
#define WK_ENTRIES (81 * 16)      // [k][f] float2{w,w} = 10.4 KB

typedef unsigned long long ull;

__device__ __forceinline__ ull pack2(float lo, float hi) {
    ull r;
    asm("mov.b64 %0, {%1, %2};" : "=l"(r) : "f"(lo), "f"(hi));
    return r;
}
__device__ __forceinline__ void unpack2(float& lo, float& hi, ull v) {
    asm("mov.b64 {%0, %1}, %2;" : "=f"(lo), "=f"(hi) : "l"(v));
}
#define FMA2(d, a, b) \
    asm("fma.rn.f32x2 %0, %1, %2, %0;" : "+l"(d) : "l"(a), "l"(b))

__global__ __launch_bounds__(128, 4)
void conv4d_kernel(const float* __restrict__ x,
                   const float* __restrict__ Wt,
                   const float* __restrict__ bias,
                   float* __restrict__ out)
{
    __shared__ float  sx[SLAB_ELEMS];
    __shared__ float2 sw2[WK_ENTRIES];   // sw2[k*16+f] = {w, w}

    const int bid = blockIdx.x;
    const int fg  = bid & 1;
    int t = bid >> 1;
    const int d = t % OD;  t /= OD;
    const int l = t % OL;
    const int n = t / OL;
    const int fbase = fg * 16;
    const int tid = threadIdx.x;

    const int ty = tid / 11;
    const int tx = tid % 11;
    const bool active = (tid < 121);
    const int oh0 = 2 * ty;
    const int ow0 = 2 * tx;

    // packed accumulators: acc2[f][0] = (out[oh0][ow0], out[oh0][ow0+1])
    //                      acc2[f][1] = (out[oh0+1][ow0], out[oh0+1][ow0+1])
    ull acc2[16][2];
#pragma unroll
    for (int f = 0; f < 16; f++) { acc2[f][0] = 0ull; acc2[f][1] = 0ull; }

    const float* xbase = x + (size_t)n * Cc * Ll * Dd * Hh * WW
                           + (size_t)l * Dd * Hh * WW
                           + (size_t)d * Hh * WW;

#pragma unroll 1
    for (int c = 0; c < Cc; c++) {
        __syncthreads();

        // ---- x slab: 9 planes x 576 floats, float4 loads ----
        const float* xc = xbase + (size_t)c * Ll * Dd * Hh * WW;
#pragma unroll 1
        for (int i4 = tid; i4 < SLAB_ELEMS / 4; i4 += 128) {
            const int p  = i4 / 144;
            const int r4 = i4 - p * 144;
            const int lk = p / 3;
            const int dk = p - lk * 3;
            const float4 v = *reinterpret_cast<const float4*>(
                xc + (size_t)lk * Dd * Hh * WW + (size_t)dk * Hh * WW + (size_t)r4 * 4);
            *reinterpret_cast<float4*>(&sx[p * 576 + r4 * 4]) = v;
        }

        // ---- weights, transposed + duplicated: sw2[k*16+f] = {w,w} ----
        // GMEM W element (f, c, k): Wt[(fbase+f)*(Cc*81) + c*81 + k]
        const float* wc = Wt + (size_t)fbase * (Cc * 81) + (size_t)c * 81;
#pragma unroll 1
        for (int i = tid; i < WK_ENTRIES; i += 128) {
            const int k  = i >> 4;
            const int ff = i & 15;
            const float w = wc[(size_t)ff * (Cc * 81) + k];
            sw2[i] = make_float2(w, w);
        }

        __syncthreads();

        if (active) {
#pragma unroll 1
            for (int p = 0; p < 9; p++) {           // plane = lk*3+dk
                const float* sxp = &sx[p * 576];
                const int kb0 = p * 9;
#pragma unroll
                for (int hk = 0; hk < 3; hk++) {
                    const float* r0 = sxp + (oh0 + hk) * 24 + ow0;
                    const float* r1 = r0 + 24;
                    // 2x4 patch via LDS.64 (8B-aligned: even float index)
                    const float2 a0 = *reinterpret_cast<const float2*>(r0);
                    const float2 a1 = *reinterpret_cast<const float2*>(r0 + 2);
                    const float2 b0 = *reinterpret_cast<const float2*>(r1);
                    const float2 b1 = *reinterpret_cast<const float2*>(r1 + 2);
                    ull xa[3], xb[3];
                    xa[0] = pack2(a0.x, a0.y);
                    xa[1] = pack2(a0.y, a1.x);
                    xa[2] = pack2(a1.x, a1.y);
                    xb[0] = pack2(b0.x, b0.y);
                    xb[1] = pack2(b0.y, b1.x);
                    xb[2] = pack2(b1.x, b1.y);
#pragma unroll
                    for (int wk = 0; wk < 3; wk++) {
                        const int k = kb0 + hk * 3 + wk;
                        const ulonglong2* wp =
                            reinterpret_cast<const ulonglong2*>(&sw2[k * 16]);
                        const ull bxa = xa[wk];
                        const ull bxb = xb[wk];
#pragma unroll
                        for (int fq = 0; fq < 8; fq++) {
                            const ulonglong2 w2 = wp[fq];   // filters 2fq, 2fq+1
                            FMA2(acc2[2 * fq]    [0], w2.x, bxa);
                            FMA2(acc2[2 * fq]    [1], w2.x, bxb);
                            FMA2(acc2[2 * fq + 1][0], w2.y, bxa);
                            FMA2(acc2[2 * fq + 1][1], w2.y, bxb);
                        }
                    }
                }
            }
        }
    }

    if (active) {
#pragma unroll
        for (int f = 0; f < 16; f++) {
            const int fglob = fbase + f;
            const float bv = 3.0f * bias[fglob];
            const size_t obase =
                ((((size_t)n * Ff + fglob) * OL + l) * OD + d) * (OH * OWc);
            float v00, v01, v10, v11;
            unpack2(v00, v01, acc2[f][0]);
            unpack2(v10, v11, acc2[f][1]);
            float2 o0 = make_float2(v00 + bv, v01 + bv);
            float2 o1 = make_float2(v10 + bv, v11 + bv);
            *reinterpret_cast<float2*>(&out[obase + (size_t)oh0 * OWc + ow0]) = o0;
            *reinterpret_cast<float2*>(&out[obase + (size_t)(oh0 + 1) * OWc + ow0]) = o1;
        }
    }
}

extern "C" void kernel_launch(void* const* d_in, const int* in_sizes, int n_in,
                              void* d_out, int out_size) {
    const float* x  = (const float*)d_in[0];
    const float* Wt = (const float*)d_in[1];
    const float* b  = (const float*)d_in[2];
    float* out = (float*)d_out;

    const int grid = Nn * OL * OD * 2;   // 10560 blocks
    conv4d_kernel<<<grid, 128>>>(x, Wt, b, out);
}

// round 5
// speedup vs baseline: 1.7672x; 1.7270x over previous
#include <cuda_runtime.h>
#include <cstdint>

// ---------------- problem constants ----------------
#define Nn 8
#define Cc 16
#define Ll 32
#define Dd 24
#define HW24 576
#define Ff 32
#define OL 30
#define OD 22
#define OE 22

// ---------------- scratch (prepped layouts) ----------------
// g_xt: [n][l][d][s=576][8 float2 slots]  (64B per spatial row, fragment-baked)
//   slot j holds pair (c_lo, c_lo+4), q = j ^ (4*((s>>1)&1)), c_lo = q<4 ? q : q+4
__device__ float g_xt[(size_t)Nn * Ll * Dd * HW24 * Cc + 1024];  // +pad for row overrun
// g_w2: [p=9][tap=9][nt=4][n=8][8 float2 slots], same pair/swizzle rule keyed on n
__device__ float g_w2[9 * 9 * 4 * 8 * 16];

__device__ __forceinline__ uint32_t tf32_rna(float x) {
    uint32_t r;
    asm("cvt.rna.tf32.f32 %0, %1;" : "=r"(r) : "f"(x));
    return r;
}

__device__ __forceinline__ void mma_tf32(float* d,
    uint32_t a0, uint32_t a1, uint32_t a2, uint32_t a3,
    uint32_t b0, uint32_t b1)
{
    asm volatile(
        "mma.sync.aligned.m16n8k8.row.col.f32.tf32.tf32.f32 "
        "{%0,%1,%2,%3}, {%4,%5,%6,%7}, {%8,%9}, {%0,%1,%2,%3};"
        : "+f"(d[0]), "+f"(d[1]), "+f"(d[2]), "+f"(d[3])
        : "r"(a0), "r"(a1), "r"(a2), "r"(a3), "r"(b0), "r"(b1));
}

// ---------------- prep: x transpose + tf32 round + fragment bake ----------------
__global__ __launch_bounds__(256)
void transpose_x(const float* __restrict__ x) {
    __shared__ float sx[Cc][HW24];
    int bid = blockIdx.x;                       // n*Ll*Dd
    int D = bid % Dd;
    int L = (bid / Dd) % Ll;
    int n = bid / (Dd * Ll);
    for (int i4 = threadIdx.x; i4 < Cc * 144; i4 += 256) {
        int c = i4 / 144, r4 = i4 - c * 144;
        const float4 v = *reinterpret_cast<const float4*>(
            x + ((((size_t)(n * Cc + c) * Ll + L) * Dd + D) * HW24 + r4 * 4));
        sx[c][r4 * 4 + 0] = v.x; sx[c][r4 * 4 + 1] = v.y;
        sx[c][r4 * 4 + 2] = v.z; sx[c][r4 * 4 + 3] = v.w;
    }
    __syncthreads();
    float2* dst = reinterpret_cast<float2*>(
        g_xt + ((size_t)(n * Ll + L) * Dd + D) * (HW24 * Cc));
    for (int idx = threadIdx.x; idx < HW24 * 8; idx += 256) {
        int s = idx >> 3, j = idx & 7;
        int q = j ^ (4 * ((s >> 1) & 1));
        int clo = (q < 4) ? q : q + 4;
        float2 v;
        v.x = __uint_as_float(tf32_rna(sx[clo][s]));
        v.y = __uint_as_float(tf32_rna(sx[clo + 4][s]));
        dst[idx] = v;
    }
}

// W[f][c][pt=81] -> g_w2, tf32-rounded, fragment-baked
__global__ __launch_bounds__(256)
void prep_w(const float* __restrict__ W) {
    for (int i = threadIdx.x; i < 9 * 9 * 4 * 8 * 8; i += 256) {
        int p = i / 2304;
        int r = i - p * 2304;
        int tap = r >> 8;                 // r / 256
        int r2 = r & 255;
        int nt = r2 >> 6;
        int nrow = (r2 >> 3) & 7;
        int j = r2 & 7;
        int q = j ^ (4 * ((nrow >> 1) & 1));
        int clo = (q < 4) ? q : q + 4;
        int f = nt * 8 + nrow;
        int pt = p * 9 + tap;
        float2 v;
        v.x = __uint_as_float(tf32_rna(W[((size_t)f * Cc + clo) * 81 + pt]));
        v.y = __uint_as_float(tf32_rna(W[((size_t)f * Cc + clo + 4) * 81 + pt]));
        reinterpret_cast<float2*>(g_w2)[i] = v;
    }
}

// ---------------- smem layout ----------------
#define SM_A 0                       // 640 rows x 64B = 40960
#define SM_B 40960                   // 9 taps x 2048B = 18432 (overlaid by stage)
#define STAGE_F (16 * 33)            // 528 floats per warp
#define SM_BIAS (40960 + 9 * STAGE_F * 4)   // 59968
#define SM_TOTAL 60160

// ---------------- main kernel ----------------
__global__ __launch_bounds__(288, 2)
void conv4d_mma(const float* __restrict__ bias, float* __restrict__ out) {
    extern __shared__ char smem[];
    float* sbias = reinterpret_cast<float*>(smem + SM_BIAS);

    const int tid  = threadIdx.x;
    const int wid  = tid >> 5;
    const int lane = tid & 31;
    const int g    = lane >> 2;        // groupID
    const int tig  = lane & 3;         // threadID in group

    int bid = blockIdx.x;
    const int d = bid % OD;
    const int l = (bid / OD) % OL;
    const int n = bid / (OD * OL);

    if (tid < Ff) sbias[tid] = 3.0f * bias[tid];

    float acc[4][4][4];
#pragma unroll
    for (int mt = 0; mt < 4; mt++)
#pragma unroll
        for (int nt = 0; nt < 4; nt++)
#pragma unroll
            for (int k = 0; k < 4; k++) acc[mt][nt][k] = 0.f;

    const int bswg = 4 * ((g >> 1) & 1);

#pragma unroll 1
    for (int p = 0; p < 9; ++p) {
        __syncthreads();
        // ---- A slab: 640 rows x 64B from slab (n, l+p/3, d+p%3), linear copy ----
        {
            const float4* src = reinterpret_cast<const float4*>(
                g_xt + ((size_t)((n * Ll + l + p / 3) * Dd) + d + p % 3) * (HW24 * Cc));
            float4* dst = reinterpret_cast<float4*>(smem + SM_A);
#pragma unroll 1
            for (int i = tid; i < 2560; i += 288) dst[i] = src[i];
        }
        // ---- B: 9 taps x 2048B for this plane ----
        {
            const float4* src = reinterpret_cast<const float4*>(g_w2 + (size_t)p * 4608);
            float4* dst = reinterpret_cast<float4*>(smem + SM_B);
#pragma unroll 1
            for (int i = tid; i < 1152; i += 288) dst[i] = src[i];
        }
        __syncthreads();

#pragma unroll 1
        for (int tap = 0; tap < 9; ++tap) {
            const int off = (tap / 3) * 24 + (tap % 3);
            // B fragments: [nt][kstep]
            uint2 bf[4][2];
#pragma unroll
            for (int nt = 0; nt < 4; nt++)
#pragma unroll
                for (int ks = 0; ks < 2; ks++) {
                    const int q = tig + 4 * ks;
                    bf[nt][ks] = *reinterpret_cast<const uint2*>(
                        smem + SM_B + tap * 2048 + nt * 512 + g * 64 + (q ^ bswg) * 8);
                }
#pragma unroll
            for (int mt = 0; mt < 4; mt++) {
                const int s0  = wid * 64 + mt * 16 + off;
                const int rA  = s0 + g;
                const int rA8 = rA + 8;
                const int swA  = 4 * ((rA  >> 1) & 1);
                const int swA8 = 4 * ((rA8 >> 1) & 1);
#pragma unroll
                for (int ks = 0; ks < 2; ks++) {
                    const int q = tig + 4 * ks;
                    const uint2 a02 = *reinterpret_cast<const uint2*>(
                        smem + SM_A + rA * 64 + (q ^ swA) * 8);
                    const uint2 a13 = *reinterpret_cast<const uint2*>(
                        smem + SM_A + rA8 * 64 + (q ^ swA8) * 8);
#pragma unroll
                    for (int nt = 0; nt < 4; nt++)
                        mma_tf32(acc[mt][nt],
                                 a02.x, a13.x, a02.y, a13.y,
                                 bf[nt][ks].x, bf[nt][ks].y);
                }
            }
        }
    }

    // ---- epilogue: stage through smem for coalesced f-major gmem stores ----
    __syncthreads();    // all warps done reading B region before overlay
    float* st = reinterpret_cast<float*>(smem + SM_B) + wid * STAGE_F;

    const int sl = lane & 15;
    const int fh = lane >> 4;

#pragma unroll 1
    for (int mt = 0; mt < 4; mt++) {
#pragma unroll
        for (int nt = 0; nt < 4; nt++) {
            const int col = nt * 8 + 2 * tig;
            st[g * 33 + col]           = acc[mt][nt][0];
            st[g * 33 + col + 1]       = acc[mt][nt][1];
            st[(g + 8) * 33 + col]     = acc[mt][nt][2];
            st[(g + 8) * 33 + col + 1] = acc[mt][nt][3];
        }
        __syncwarp();
        const int s  = wid * 64 + mt * 16 + sl;
        const int oh = s / 24;
        const int ow = s - oh * 24;
        if (oh < OE && ow < OE) {
            const size_t base = ((((size_t)n * Ff) * OL + l) * OD + d) * (OE * OE)
                                + (size_t)oh * OE + ow;
            const size_t fstr = (size_t)OL * OD * OE * OE;   // 319440
#pragma unroll
            for (int fp = 0; fp < 16; fp++) {
                const int f = fp * 2 + fh;
                out[base + (size_t)f * fstr] = st[sl * 33 + f] + sbias[f];
            }
        }
        __syncwarp();
    }
}

// ---------------- launch ----------------
extern "C" void kernel_launch(void* const* d_in, const int* in_sizes, int n_in,
                              void* d_out, int out_size) {
    const float* x  = (const float*)d_in[0];
    const float* Wt = (const float*)d_in[1];
    const float* b  = (const float*)d_in[2];
    float* out = (float*)d_out;

    transpose_x<<<Nn * Ll * Dd, 256>>>(x);
    prep_w<<<1, 256>>>(Wt);

    static int cfg_done = 0;
    if (!cfg_done) {
        cudaFuncSetAttribute(conv4d_mma,
                             cudaFuncAttributeMaxDynamicSharedMemorySize, SM_TOTAL);
        cfg_done = 1;
    }
    conv4d_mma<<<Nn * OL * OD, 288, SM_TOTAL>>>(b, out);
}